// round 4
// baseline (speedup 1.0000x reference)
#include <cuda_runtime.h>
#include <cuda_bf16.h>
#include <math.h>

#define BATCH 8
#define HDIM  512
#define WDIM  512
#define NPATCH 1024
#define PATCH 16
#define NCELL 32
#define GCH   20
#define FEAT  64
#define IMG   (HDIM*WDIM)

// Scratch (no allocation allowed)
__device__ unsigned long long g_bmax[BATCH * 256];
__device__ float g_corr[BATCH * 2 * NCELL * NCELL];
__device__ int   g_bar = 0;

// ---------------------------------------------------------------------------
// Kernel 1: per-patch entropy, warp per patch, block = 4 patches.
// grid (256, 8), block 128. Emits per-block argmax candidate (packed u64).
// ---------------------------------------------------------------------------
__global__ __launch_bounds__(128) void ent_kernel(const float* __restrict__ HE) {
    __shared__ int hist[4][256];
    __shared__ unsigned long long keys[4];

    const int t = threadIdx.x, warp = t >> 5, lane = t & 31;
    const int p = blockIdx.x * 4 + warp;
    const int b = blockIdx.y;
    const int y00 = (p >> 5) * PATCH;
    const int x00 = (p & 31) * PATCH;
    const float* base = HE + (size_t)b * 3 * IMG;

    const size_t off = (size_t)(y00 + (lane >> 1)) * WDIM + x00 + (lane & 1) * 8;
    const float4 r0 = *(const float4*)(base + off);
    const float4 r1 = *(const float4*)(base + off + 4);
    const float4 g0 = *(const float4*)(base + IMG + off);
    const float4 g1 = *(const float4*)(base + IMG + off + 4);
    const float4 b0 = *(const float4*)(base + 2 * IMG + off);
    const float4 b1 = *(const float4*)(base + 2 * IMG + off + 4);

    float gv[8];
    gv[0] = 0.2989f * r0.x + 0.587f * g0.x + 0.114f * b0.x;
    gv[1] = 0.2989f * r0.y + 0.587f * g0.y + 0.114f * b0.y;
    gv[2] = 0.2989f * r0.z + 0.587f * g0.z + 0.114f * b0.z;
    gv[3] = 0.2989f * r0.w + 0.587f * g0.w + 0.114f * b0.w;
    gv[4] = 0.2989f * r1.x + 0.587f * g1.x + 0.114f * b1.x;
    gv[5] = 0.2989f * r1.y + 0.587f * g1.y + 0.114f * b1.y;
    gv[6] = 0.2989f * r1.z + 0.587f * g1.z + 0.114f * b1.z;
    gv[7] = 0.2989f * r1.w + 0.587f * g1.w + 0.114f * b1.w;

    float mn = gv[0], mx = gv[0];
    #pragma unroll
    for (int j = 1; j < 8; j++) { mn = fminf(mn, gv[j]); mx = fmaxf(mx, gv[j]); }
    #pragma unroll
    for (int o = 16; o > 0; o >>= 1) {
        mn = fminf(mn, __shfl_xor_sync(0xffffffffu, mn, o));
        mx = fmaxf(mx, __shfl_xor_sync(0xffffffffu, mx, o));
    }

    ((int4*)hist[warp])[lane]      = make_int4(0, 0, 0, 0);
    ((int4*)hist[warp])[lane + 32] = make_int4(0, 0, 0, 0);
    __syncwarp();

    const float den = (mx - mn) + 1e-8f;
    const float rs = 256.0f / den;
    #pragma unroll
    for (int j = 0; j < 8; j++) {
        const float r = gv[j] - mn;
        const float q = r * rs;
        const float fq = floorf(q);
        int bin;
        const float frac = q - fq;
        if (frac < 5e-4f || frac > 1.0f - 5e-4f) {
            bin = (int)((r / den) * 256.0f);      // exact reference path
        } else {
            bin = (int)fq;
        }
        bin = min(255, max(0, bin));
        atomicAdd(&hist[warp][bin], 1);
    }
    __syncwarp();

    const int4 c0 = ((const int4*)hist[warp])[lane];
    const int4 c1 = ((const int4*)hist[warp])[lane + 32];
    float e = 0.0f;
    {
        const int cs[8] = {c0.x, c0.y, c0.z, c0.w, c1.x, c1.y, c1.z, c1.w};
        #pragma unroll
        for (int j = 0; j < 8; j++) {
            if (cs[j] > 0) {
                const float pr = (float)cs[j] * (1.0f / 256.0f);
                e += pr * log2f(pr);
            }
        }
    }
    #pragma unroll
    for (int o = 16; o > 0; o >>= 1) e += __shfl_xor_sync(0xffffffffu, e, o);

    const float ent = fmaxf(-e, 0.0f);
    const unsigned long long key =
        ((unsigned long long)__float_as_uint(ent) << 32) | (unsigned)(NPATCH - 1 - p);
    if (lane == 0) keys[warp] = key;
    __syncthreads();
    if (t == 0) {
        unsigned long long k = keys[0];
        #pragma unroll
        for (int w = 1; w < 4; w++) k = (keys[w] > k) ? keys[w] : k;
        g_bmax[b * 256 + blockIdx.x] = k;
    }
}

// ---------------------------------------------------------------------------
// Kernel 2: argmax + stats + GNN + corr (+ fused SSIM). grid (8,2), block 1024.
// ---------------------------------------------------------------------------

// shared pool layout (floats). Row stride 68 (16B aligned: 68*4=272).
#define STR   68
#define OFF_X     0                      // X[32][68] = 2176
#define OFF_ADJ   2176                   // adj[32][33] = 1056
#define OFF_COORD 3232                   // coords[32][2]
#define OFF_ROWS  3296                   // rowsum[32]
#define OFF_OV    3328                   // chS(5120) | Gs(2176)+buf(2176)+ws(4352)
#define POOLSZ    (3328 + 8704)          // 12032 floats = 48128 B

template<int NCH>
__device__ __forceinline__ void do_stats(
    const int* __restrict__ mb, const float* __restrict__ chS,
    float* __restrict__ Xs, float* __restrict__ coordS,
    int lane, int cell, int y0, int x0)
{
    // lane covers 8 contiguous pixels [lane*8, lane*8+8)
    const int py  = lane >> 1;
    const int px0 = (lane & 1) * 8;
    const int* mrow = mb + ((size_t)cell * HDIM + y0 + py) * WDIM + x0 + px0;
    const int4 m0 = *(const int4*)(mrow);
    const int4 m1 = *(const int4*)(mrow + 4);
    float mv[8];
    mv[0] = (float)m0.x; mv[1] = (float)m0.y; mv[2] = (float)m0.z; mv[3] = (float)m0.w;
    mv[4] = (float)m1.x; mv[5] = (float)m1.y; mv[6] = (float)m1.z; mv[7] = (float)m1.w;

    float sm = 0.0f, sx = 0.0f, sy = 0.0f;
    #pragma unroll
    for (int j = 0; j < 8; j++) {
        sm += mv[j];
        sx += mv[j] * (float)(px0 + j);
        sy += mv[j] * (float)py;
    }

    float acc[NCH];
    #pragma unroll
    for (int c = 0; c < NCH; c++) {
        const float4 f0 = *(const float4*)&chS[c * 256 + lane * 8];
        const float4 f1 = *(const float4*)&chS[c * 256 + lane * 8 + 4];
        float a = 0.0f;
        a += mv[0] * f0.x; a += mv[1] * f0.y; a += mv[2] * f0.z; a += mv[3] * f0.w;
        a += mv[4] * f1.x; a += mv[5] * f1.y; a += mv[6] * f1.z; a += mv[7] * f1.w;
        acc[c] = a;
    }

    #pragma unroll
    for (int o = 16; o > 0; o >>= 1) {
        sm += __shfl_down_sync(0xffffffffu, sm, o);
        sx += __shfl_down_sync(0xffffffffu, sx, o);
        sy += __shfl_down_sync(0xffffffffu, sy, o);
        #pragma unroll
        for (int c = 0; c < NCH; c++) acc[c] += __shfl_down_sync(0xffffffffu, acc[c], o);
    }
    if (lane == 0) {
        const float denom = sm + 1e-6f;
        #pragma unroll
        for (int c = 0; c < NCH; c++) Xs[cell * STR + c] = acc[c] / denom;
        coordS[cell * 2 + 0] = sx / sm;
        coordS[cell * 2 + 1] = sy / sm;
    }
}

__global__ __launch_bounds__(1024) void graph_kernel(
    const float* __restrict__ HE, const float* __restrict__ HQ,
    const int* __restrict__ MASK,
    const float* __restrict__ w1, const float* __restrict__ b1,
    const float* __restrict__ w2, const float* __restrict__ b2,
    float* __restrict__ out)
{
    __shared__ __align__(16) float pool[POOLSZ];
    __shared__ int s_sel;

    const int b = blockIdx.x;
    const int pass = blockIdx.y;
    const int t = threadIdx.x;
    const int lane = t & 31, warp = t >> 5;

    float* Xs     = pool + OFF_X;
    float* adjs   = pool + OFF_ADJ;
    float* coordS = pool + OFF_COORD;
    float* rowS   = pool + OFF_ROWS;
    float* ov     = pool + OFF_OV;

    // ---- argmax over 256 per-block candidates (warp 0) ----
    if (t < 32) {
        unsigned long long k = 0ull;
        #pragma unroll
        for (int j = 0; j < 8; j++) {
            const unsigned long long v = g_bmax[b * 256 + t + 32 * j];
            k = (v > k) ? v : k;
        }
        #pragma unroll
        for (int o = 16; o > 0; o >>= 1) {
            const unsigned long long v = __shfl_xor_sync(0xffffffffu, k, o);
            k = (v > k) ? v : k;
        }
        if (t == 0) s_sel = NPATCH - 1 - (int)(unsigned)(k & 0xffffffffu);
    }
    __syncthreads();
    const int sel = s_sel;
    const int y0 = (sel >> 5) * PATCH;
    const int x0 = (sel & 31) * PATCH;

    // ---- stage channels into shared (float4 both sides), zero X ----
    const int nch = pass ? GCH : 3;
    const float* src = pass ? (HQ + (size_t)b * GCH * IMG) : (HE + (size_t)b * 3 * IMG);
    for (int i = t; i < nch * 64; i += 1024) {
        const int c = i >> 6, chunk = i & 63;
        const int py = chunk >> 2, px = (chunk & 3) * 4;
        *(float4*)&ov[c * 256 + chunk * 4] =
            *(const float4*)&src[(size_t)c * IMG + (size_t)(y0 + py) * WDIM + x0 + px];
    }
    for (int i = t; i < NCELL * STR; i += 1024) Xs[i] = 0.0f;
    __syncthreads();

    // ---- per-cell masked stats: warp = cell ----
    const int* mb = MASK + (size_t)b * NCELL * IMG;
    if (pass == 0) do_stats<3>(mb, ov, Xs, coordS, lane, warp, y0, x0);
    else           do_stats<GCH>(mb, ov, Xs, coordS, lane, warp, y0, x0);
    __syncthreads();

    // ---- adjacency ----
    if (t < NCELL * NCELL) {
        const int r_ = t >> 5, c_ = t & 31;
        const float dx = coordS[r_ * 2] - coordS[c_ * 2];
        const float dy = coordS[r_ * 2 + 1] - coordS[c_ * 2 + 1];
        const float dist = sqrtf(fmaxf(dx * dx + dy * dy, 0.0f));
        adjs[r_ * 33 + c_] = expf(-dist / 3.000001f);
    }
    __syncthreads();
    if (t < NCELL) {
        float s = 0.0f;
        #pragma unroll
        for (int k = 0; k < NCELL; k++) s += adjs[t * 33 + k];
        rowS[t] = s + 1e-8f;
    }
    __syncthreads();
    if (t < NCELL * NCELL) {
        const int r_ = t >> 5, c_ = t & 31;
        adjs[r_ * 33 + c_] /= rowS[r_];
    }

    float* Gs   = ov;               // [32][68]
    float* bufS = ov + 2176;        // [32][68]
    float* ws   = ov + 4352;        // [64][68]

    // ws = w1^T
    for (int i = t; i < FEAT * FEAT; i += 1024)
        ws[(i & 63) * STR + (i >> 6)] = w1[i];
    __syncthreads();

    const int r_ = t >> 5;          // 0..31
    const int c2 = (t & 31) * 2;    // even col 0..62

    // m1: bufS = adj @ X
    {
        float ax = 0.0f, ay = 0.0f;
        #pragma unroll
        for (int k = 0; k < NCELL; k++) {
            const float a = adjs[r_ * 33 + k];
            const float2 x = *(const float2*)&Xs[k * STR + c2];
            ax += a * x.x; ay += a * x.y;
        }
        *(float2*)&bufS[r_ * STR + c2] = make_float2(ax, ay);
    }
    __syncthreads();

    // m2: Gs = relu(bufS @ w1^T + b1)
    {
        float ax = 0.0f, ay = 0.0f;
        #pragma unroll
        for (int k = 0; k < FEAT; k++) {
            const float tv = bufS[r_ * STR + k];
            const float2 w = *(const float2*)&ws[k * STR + c2];
            ax += tv * w.x; ay += tv * w.y;
        }
        *(float2*)&Gs[r_ * STR + c2] =
            make_float2(fmaxf(ax + b1[c2], 0.0f), fmaxf(ay + b1[c2 + 1], 0.0f));
    }
    __syncthreads();

    // m3: bufS = adj @ Gs
    {
        float ax = 0.0f, ay = 0.0f;
        #pragma unroll
        for (int k = 0; k < NCELL; k++) {
            const float a = adjs[r_ * 33 + k];
            const float2 x = *(const float2*)&Gs[k * STR + c2];
            ax += a * x.x; ay += a * x.y;
        }
        *(float2*)&bufS[r_ * STR + c2] = make_float2(ax, ay);
    }
    __syncthreads();
    // ws = w2^T
    for (int i = t; i < FEAT * FEAT; i += 1024)
        ws[(i & 63) * STR + (i >> 6)] = w2[i];
    __syncthreads();

    // m4: Gs = relu(bufS @ w2^T + b2)
    {
        float ax = 0.0f, ay = 0.0f;
        #pragma unroll
        for (int k = 0; k < FEAT; k++) {
            const float tv = bufS[r_ * STR + k];
            const float2 w = *(const float2*)&ws[k * STR + c2];
            ax += tv * w.x; ay += tv * w.y;
        }
        *(float2*)&Gs[r_ * STR + c2] =
            make_float2(fmaxf(ax + b2[c2], 0.0f), fmaxf(ay + b2[c2 + 1], 0.0f));
    }
    __syncthreads();

    // ---- standardize columns (over 32 rows, ddof=1) ----
    if (t < 128) {
        float* M = (t < 64) ? (Xs + t) : (Gs + (t - 64));
        float mean = 0.0f;
        #pragma unroll
        for (int rr = 0; rr < NCELL; rr++) mean += M[rr * STR];
        mean *= (1.0f / (float)NCELL);
        float vs = 0.0f;
        #pragma unroll
        for (int rr = 0; rr < NCELL; rr++) {
            const float d = M[rr * STR] - mean;
            vs += d * d;
        }
        const float dn = sqrtf(vs / (float)(NCELL - 1)) + 1e-6f;
        #pragma unroll
        for (int rr = 0; rr < NCELL; rr++) M[rr * STR] = (M[rr * STR] - mean) / dn;
    }
    __syncthreads();

    // ---- corr = clip(Z Z^T / 127, -1, 1): one output per thread ----
    {
        const int cr = t >> 5, cc = t & 31;
        float acc = 0.0f;
        #pragma unroll
        for (int kk = 0; kk < 16; kk++) {
            const float4 a = *(const float4*)&Xs[cr * STR + kk * 4];
            const float4 v = *(const float4*)&Xs[cc * STR + kk * 4];
            acc += a.x * v.x; acc += a.y * v.y; acc += a.z * v.z; acc += a.w * v.w;
        }
        #pragma unroll
        for (int kk = 0; kk < 16; kk++) {
            const float4 a = *(const float4*)&Gs[cr * STR + kk * 4];
            const float4 v = *(const float4*)&Gs[cc * STR + kk * 4];
            acc += a.x * v.x; acc += a.y * v.y; acc += a.z * v.z; acc += a.w * v.w;
        }
        float v = acc * (1.0f / 127.0f);
        v = fminf(1.0f, fmaxf(-1.0f, v));
        g_corr[((size_t)b * 2 + pass) * (NCELL * NCELL) + cr * NCELL + cc] = v;
    }

    // ---- inter-block barrier (16 co-resident blocks) ----
    __threadfence();
    __syncthreads();
    if (t == 0) atomicAdd(&g_bar, 1);
    if (b != 0 || pass != 0) return;

    if (t == 0) {
        volatile int* vb = &g_bar;
        while (*vb < 16) { }
    }
    __syncthreads();
    __threadfence();

    // ---- fused SSIM: warp w -> image w (warps 0..7) + fixed-order mean ----
    float* sl = pool;
    if (warp < BATCH) {
        const float* cx = g_corr + (size_t)warp * 2048;
        const float* cy = cx + 1024;
        float sx = 0.0f, sy = 0.0f;
        for (int i = lane; i < 1024; i += 32) { sx += cx[i]; sy += cy[i]; }
        #pragma unroll
        for (int o = 16; o > 0; o >>= 1) {
            sx += __shfl_xor_sync(0xffffffffu, sx, o);
            sy += __shfl_xor_sync(0xffffffffu, sy, o);
        }
        const float mux = sx / 1024.0f;
        const float muy = sy / 1024.0f;
        float ax = 0.0f, ay = 0.0f, axy = 0.0f;
        for (int i = lane; i < 1024; i += 32) {
            const float dx = cx[i] - mux;
            const float dy = cy[i] - muy;
            ax += dx * dx; ay += dy * dy; axy += dx * dy;
        }
        #pragma unroll
        for (int o = 16; o > 0; o >>= 1) {
            ax  += __shfl_xor_sync(0xffffffffu, ax, o);
            ay  += __shfl_xor_sync(0xffffffffu, ay, o);
            axy += __shfl_xor_sync(0xffffffffu, axy, o);
        }
        if (lane == 0) {
            const float vx = ax / 1023.0f, vy = ay / 1023.0f, cxy = axy / 1024.0f;
            const float C1 = 1e-4f, C2 = 1e-4f;
            const float num = (2.0f * mux * muy + C1) * (2.0f * cxy + C2);
            const float den = (mux * mux + muy * muy + C1) * (vx + vy + C2);
            float ssim = num / den;
            ssim = fminf(1.0f, fmaxf(0.0f, ssim));
            sl[warp] = 1.0f - ssim;
        }
    }
    __syncthreads();
    if (t == 0) {
        float s = 0.0f;
        #pragma unroll
        for (int i = 0; i < BATCH; i++) s += sl[i];
        out[0] = s / (float)BATCH;
        g_bar = 0;
    }
}

extern "C" void kernel_launch(void* const* d_in, const int* in_sizes, int n_in,
                              void* d_out, int out_size) {
    (void)in_sizes; (void)n_in; (void)out_size;
    const float* HE   = (const float*)d_in[0];
    const float* HQ   = (const float*)d_in[1];
    const int*   MASK = (const int*)d_in[2];
    const float* w1   = (const float*)d_in[3];
    const float* b1   = (const float*)d_in[4];
    const float* w2   = (const float*)d_in[5];
    const float* b2   = (const float*)d_in[6];

    ent_kernel<<<dim3(256, BATCH), 128>>>(HE);
    graph_kernel<<<dim3(BATCH, 2), 1024>>>(HE, HQ, MASK, w1, b1, w2, b2, (float*)d_out);
}

// round 5
// speedup vs baseline: 1.0040x; 1.0040x over previous
#include <cuda_runtime.h>
#include <cuda_bf16.h>
#include <math.h>

#define BATCH 8
#define HDIM  512
#define WDIM  512
#define NPATCH 1024
#define PATCH 16
#define NCELL 32
#define GCH   20
#define FEAT  64
#define IMG   (HDIM*WDIM)
#define STR   68                 // padded row stride (16B-aligned, 4*odd)

// Scratch (no allocation allowed)
__device__ unsigned long long g_bmax[BATCH * 256];
__device__ float g_corr[BATCH * 2 * NCELL * NCELL];
__device__ int   g_bar = 0;

// ---------------------------------------------------------------------------
// Kernel 1: per-patch entropy, warp per patch. grid (256,8), block 128.
// ---------------------------------------------------------------------------
__global__ __launch_bounds__(128) void ent_kernel(const float* __restrict__ HE) {
    __shared__ int hist[4][256];
    __shared__ unsigned long long keys[4];

    const int t = threadIdx.x, warp = t >> 5, lane = t & 31;
    const int p = blockIdx.x * 4 + warp;
    const int b = blockIdx.y;
    const int y00 = (p >> 5) * PATCH;
    const int x00 = (p & 31) * PATCH;
    const float* base = HE + (size_t)b * 3 * IMG;

    const size_t off = (size_t)(y00 + (lane >> 1)) * WDIM + x00 + (lane & 1) * 8;
    const float4 r0 = *(const float4*)(base + off);
    const float4 r1 = *(const float4*)(base + off + 4);
    const float4 g0 = *(const float4*)(base + IMG + off);
    const float4 g1 = *(const float4*)(base + IMG + off + 4);
    const float4 b0 = *(const float4*)(base + 2 * IMG + off);
    const float4 b1 = *(const float4*)(base + 2 * IMG + off + 4);

    float gv[8];
    gv[0] = 0.2989f * r0.x + 0.587f * g0.x + 0.114f * b0.x;
    gv[1] = 0.2989f * r0.y + 0.587f * g0.y + 0.114f * b0.y;
    gv[2] = 0.2989f * r0.z + 0.587f * g0.z + 0.114f * b0.z;
    gv[3] = 0.2989f * r0.w + 0.587f * g0.w + 0.114f * b0.w;
    gv[4] = 0.2989f * r1.x + 0.587f * g1.x + 0.114f * b1.x;
    gv[5] = 0.2989f * r1.y + 0.587f * g1.y + 0.114f * b1.y;
    gv[6] = 0.2989f * r1.z + 0.587f * g1.z + 0.114f * b1.z;
    gv[7] = 0.2989f * r1.w + 0.587f * g1.w + 0.114f * b1.w;

    float mn = gv[0], mx = gv[0];
    #pragma unroll
    for (int j = 1; j < 8; j++) { mn = fminf(mn, gv[j]); mx = fmaxf(mx, gv[j]); }
    #pragma unroll
    for (int o = 16; o > 0; o >>= 1) {
        mn = fminf(mn, __shfl_xor_sync(0xffffffffu, mn, o));
        mx = fmaxf(mx, __shfl_xor_sync(0xffffffffu, mx, o));
    }

    ((int4*)hist[warp])[lane]      = make_int4(0, 0, 0, 0);
    ((int4*)hist[warp])[lane + 32] = make_int4(0, 0, 0, 0);
    __syncwarp();

    const float den = (mx - mn) + 1e-8f;
    const float rs = 256.0f / den;
    #pragma unroll
    for (int j = 0; j < 8; j++) {
        const float r = gv[j] - mn;
        const float q = r * rs;
        const float fq = floorf(q);
        int bin;
        const float frac = q - fq;
        if (frac < 5e-4f || frac > 1.0f - 5e-4f) {
            bin = (int)((r / den) * 256.0f);      // exact reference path
        } else {
            bin = (int)fq;
        }
        bin = min(255, max(0, bin));
        atomicAdd(&hist[warp][bin], 1);
    }
    __syncwarp();

    const int4 c0 = ((const int4*)hist[warp])[lane];
    const int4 c1 = ((const int4*)hist[warp])[lane + 32];
    float e = 0.0f;
    {
        const int cs[8] = {c0.x, c0.y, c0.z, c0.w, c1.x, c1.y, c1.z, c1.w};
        #pragma unroll
        for (int j = 0; j < 8; j++) {
            if (cs[j] > 0) {
                const float pr = (float)cs[j] * (1.0f / 256.0f);
                e += pr * log2f(pr);
            }
        }
    }
    #pragma unroll
    for (int o = 16; o > 0; o >>= 1) e += __shfl_xor_sync(0xffffffffu, e, o);

    const float ent = fmaxf(-e, 0.0f);
    const unsigned long long key =
        ((unsigned long long)__float_as_uint(ent) << 32) | (unsigned)(NPATCH - 1 - p);
    if (lane == 0) keys[warp] = key;
    __syncthreads();
    if (t == 0) {
        unsigned long long k = keys[0];
        #pragma unroll
        for (int w = 1; w < 4; w++) k = (keys[w] > k) ? keys[w] : k;
        g_bmax[b * 256 + blockIdx.x] = k;
    }
}

// ---------------------------------------------------------------------------
// Kernel 2: argmax + stats + GNN + corr (+ fused SSIM). grid (8,2), block 512.
// ---------------------------------------------------------------------------

// pool layout (floats): X[32][68]=2176 | adj[32][33]=1056 | coord 64 | rows 32
// | ov 8704 { chS(<=5120)  OR  Gs 2176 + buf 2176 + ws 4352 }
#define POOLSZ 12032   // 48128 B

template<int NCH>
__device__ __forceinline__ void do_stats(
    const int* __restrict__ mb, const float* __restrict__ chS,
    float* __restrict__ Xs, float* __restrict__ coordS,
    int lane, int warp, int y0, int x0)
{
    for (int cell = warp * 2; cell < warp * 2 + 2; cell++) {
        const int py  = lane >> 1;
        const int px0 = (lane & 1) * 8;
        const int* mrow = mb + ((size_t)cell * HDIM + y0 + py) * WDIM + x0 + px0;
        const int4 m0 = *(const int4*)(mrow);
        const int4 m1 = *(const int4*)(mrow + 4);
        float mv[8];
        mv[0] = (float)m0.x; mv[1] = (float)m0.y; mv[2] = (float)m0.z; mv[3] = (float)m0.w;
        mv[4] = (float)m1.x; mv[5] = (float)m1.y; mv[6] = (float)m1.z; mv[7] = (float)m1.w;

        float sm = 0.0f, sx = 0.0f, sy = 0.0f;
        #pragma unroll
        for (int j = 0; j < 8; j++) {
            sm += mv[j];
            sx += mv[j] * (float)(px0 + j);
            sy += mv[j] * (float)py;
        }

        float acc[NCH];
        #pragma unroll
        for (int c = 0; c < NCH; c++) {
            const float4 f0 = *(const float4*)&chS[c * 256 + lane * 8];
            const float4 f1 = *(const float4*)&chS[c * 256 + lane * 8 + 4];
            float a = 0.0f;
            a += mv[0] * f0.x; a += mv[1] * f0.y; a += mv[2] * f0.z; a += mv[3] * f0.w;
            a += mv[4] * f1.x; a += mv[5] * f1.y; a += mv[6] * f1.z; a += mv[7] * f1.w;
            acc[c] = a;
        }

        #pragma unroll
        for (int o = 16; o > 0; o >>= 1) {
            sm += __shfl_down_sync(0xffffffffu, sm, o);
            sx += __shfl_down_sync(0xffffffffu, sx, o);
            sy += __shfl_down_sync(0xffffffffu, sy, o);
            #pragma unroll
            for (int c = 0; c < NCH; c++) acc[c] += __shfl_down_sync(0xffffffffu, acc[c], o);
        }
        if (lane == 0) {
            const float denom = sm + 1e-6f;
            #pragma unroll
            for (int c = 0; c < NCH; c++) Xs[cell * STR + c] = acc[c] / denom;
            coordS[cell * 2 + 0] = sx / sm;
            coordS[cell * 2 + 1] = sy / sm;
        }
    }
}

template<int NCH>
__device__ __forceinline__ void graph_body(
    const float* __restrict__ src, const int* __restrict__ mb,
    const float* __restrict__ w1, const float* __restrict__ b1,
    const float* __restrict__ w2, const float* __restrict__ b2,
    float* __restrict__ out, float* pool, int* s_sel_p, int b, int pass)
{
    const int t = threadIdx.x;
    const int lane = t & 31, warp = t >> 5;

    float* Xs     = pool;
    float* adjs   = pool + 2176;
    float* coordS = pool + 3232;
    float* rowS   = pool + 3296;
    float* ov     = pool + 3328;
    float* Gs   = ov;
    float* bufS = ov + 2176;
    float* ws   = ov + 4352;

    // ---- argmax over 256 per-block candidates (warp 0) ----
    if (t < 32) {
        unsigned long long k = 0ull;
        #pragma unroll
        for (int j = 0; j < 8; j++) {
            const unsigned long long v = g_bmax[b * 256 + t + 32 * j];
            k = (v > k) ? v : k;
        }
        #pragma unroll
        for (int o = 16; o > 0; o >>= 1) {
            const unsigned long long v = __shfl_xor_sync(0xffffffffu, k, o);
            k = (v > k) ? v : k;
        }
        if (t == 0) *s_sel_p = NPATCH - 1 - (int)(unsigned)(k & 0xffffffffu);
    }
    __syncthreads();
    const int sel = *s_sel_p;
    const int y0 = (sel >> 5) * PATCH;
    const int x0 = (sel & 31) * PATCH;

    // ---- stage channels into shared (float4 both sides) ----
    for (int i = t; i < NCH * 64; i += 512) {
        const int c = i >> 6, chunk = i & 63;
        const int py = chunk >> 2, px = (chunk & 3) * 4;
        *(float4*)&ov[c * 256 + chunk * 4] =
            *(const float4*)&src[(size_t)c * IMG + (size_t)(y0 + py) * WDIM + x0 + px];
    }
    __syncthreads();

    // ---- per-cell masked stats (16 warps x 2 cells). X cols >= NCH never touched.
    do_stats<NCH>(mb, ov, Xs, coordS, lane, warp, y0, x0);
    __syncthreads();

    // ---- adjacency ----
    for (int i = t; i < NCELL * NCELL; i += 512) {
        const int r_ = i >> 5, c_ = i & 31;
        const float dx = coordS[r_ * 2] - coordS[c_ * 2];
        const float dy = coordS[r_ * 2 + 1] - coordS[c_ * 2 + 1];
        const float dist = sqrtf(fmaxf(dx * dx + dy * dy, 0.0f));
        adjs[r_ * 33 + c_] = expf(-dist / 3.000001f);
    }
    __syncthreads();
    if (t < NCELL) {
        float s = 0.0f;
        #pragma unroll
        for (int k = 0; k < NCELL; k++) s += adjs[t * 33 + k];
        rowS[t] = s + 1e-8f;
    }
    __syncthreads();
    // normalize adj + load w1^T (same phase; disjoint)
    for (int i = t; i < NCELL * NCELL; i += 512) adjs[(i >> 5) * 33 + (i & 31)] /= rowS[i >> 5];
    for (int i = t; i < FEAT * FEAT; i += 512) ws[(i & 63) * STR + (i >> 6)] = w1[i];
    __syncthreads();

    // m1: bufS[32][NCH] = adj @ X (only NCH columns exist)
    for (int o = t; o < NCELL * NCH; o += 512) {
        const int r = o / NCH, c = o - r * NCH;
        float acc = 0.0f;
        #pragma unroll
        for (int k = 0; k < NCELL; k++) acc += adjs[r * 33 + k] * Xs[k * STR + c];
        bufS[r * STR + c] = acc;
    }
    __syncthreads();

    const int r_ = t >> 4;          // 0..31
    const int c4 = (t & 15) * 4;    // 0,4,...,60

    // m2: Gs = relu(bufS @ w1^T + b1), K = NCH (rest of K is exactly zero)
    {
        float a0 = 0, a1 = 0, a2 = 0, a3 = 0;
        #pragma unroll
        for (int k = 0; k < NCH; k++) {
            const float tv = bufS[r_ * STR + k];
            const float4 w = *(const float4*)&ws[k * STR + c4];
            a0 += tv * w.x; a1 += tv * w.y; a2 += tv * w.z; a3 += tv * w.w;
        }
        const float4 bb = *(const float4*)&b1[c4];
        *(float4*)&Gs[r_ * STR + c4] = make_float4(
            fmaxf(a0 + bb.x, 0.0f), fmaxf(a1 + bb.y, 0.0f),
            fmaxf(a2 + bb.z, 0.0f), fmaxf(a3 + bb.w, 0.0f));
    }
    __syncthreads();

    // m3: bufS = adj @ Gs (K=32) + load w2^T (ws free after m2)
    {
        float a0 = 0, a1 = 0, a2 = 0, a3 = 0;
        #pragma unroll
        for (int k = 0; k < NCELL; k++) {
            const float a = adjs[r_ * 33 + k];
            const float4 g = *(const float4*)&Gs[k * STR + c4];
            a0 += a * g.x; a1 += a * g.y; a2 += a * g.z; a3 += a * g.w;
        }
        *(float4*)&bufS[r_ * STR + c4] = make_float4(a0, a1, a2, a3);
    }
    for (int i = t; i < FEAT * FEAT; i += 512) ws[(i & 63) * STR + (i >> 6)] = w2[i];
    __syncthreads();

    // m4: Gs = relu(bufS @ w2^T + b2), K = 64
    {
        float a0 = 0, a1 = 0, a2 = 0, a3 = 0;
        #pragma unroll
        for (int k = 0; k < FEAT; k++) {
            const float tv = bufS[r_ * STR + k];
            const float4 w = *(const float4*)&ws[k * STR + c4];
            a0 += tv * w.x; a1 += tv * w.y; a2 += tv * w.z; a3 += tv * w.w;
        }
        const float4 bb = *(const float4*)&b2[c4];
        *(float4*)&Gs[r_ * STR + c4] = make_float4(
            fmaxf(a0 + bb.x, 0.0f), fmaxf(a1 + bb.y, 0.0f),
            fmaxf(a2 + bb.z, 0.0f), fmaxf(a3 + bb.w, 0.0f));
    }
    __syncthreads();

    // ---- standardize the NCH live X cols + 64 G cols (ddof=1). Zero cols stay 0.
    if (t < NCH + FEAT) {
        float* M = (t < NCH) ? (Xs + t) : (Gs + (t - NCH));
        float mean = 0.0f;
        #pragma unroll
        for (int rr = 0; rr < NCELL; rr++) mean += M[rr * STR];
        mean *= (1.0f / (float)NCELL);
        float vs = 0.0f;
        #pragma unroll
        for (int rr = 0; rr < NCELL; rr++) {
            const float d = M[rr * STR] - mean;
            vs += d * d;
        }
        const float dn = sqrtf(vs / (float)(NCELL - 1)) + 1e-6f;
        #pragma unroll
        for (int rr = 0; rr < NCELL; rr++) M[rr * STR] = (M[rr * STR] - mean) / dn;
    }
    __syncthreads();

    // ---- corr = clip(Z Z^T / 127, -1, 1): symmetric, upper triangle + mirror ----
    {
        float* dst = g_corr + ((size_t)b * 2 + pass) * (NCELL * NCELL);
        for (int i = t; i < NCELL * NCELL; i += 512) {
            const int cr = i >> 5, cc = i & 31;
            if (cr > cc) continue;
            float acc = 0.0f;
            if (NCH == GCH) {
                #pragma unroll
                for (int kk = 0; kk < 5; kk++) {
                    const float4 a = *(const float4*)&Xs[cr * STR + kk * 4];
                    const float4 v = *(const float4*)&Xs[cc * STR + kk * 4];
                    acc += a.x * v.x; acc += a.y * v.y; acc += a.z * v.z; acc += a.w * v.w;
                }
            } else {
                #pragma unroll
                for (int kk = 0; kk < NCH; kk++) acc += Xs[cr * STR + kk] * Xs[cc * STR + kk];
            }
            #pragma unroll
            for (int kk = 0; kk < 16; kk++) {
                const float4 a = *(const float4*)&Gs[cr * STR + kk * 4];
                const float4 v = *(const float4*)&Gs[cc * STR + kk * 4];
                acc += a.x * v.x; acc += a.y * v.y; acc += a.z * v.z; acc += a.w * v.w;
            }
            float v = acc * (1.0f / 127.0f);
            v = fminf(1.0f, fmaxf(-1.0f, v));
            dst[cr * NCELL + cc] = v;
            dst[cc * NCELL + cr] = v;
        }
    }

    // ---- inter-block barrier (16 co-resident blocks) ----
    __threadfence();
    __syncthreads();
    if (t == 0) atomicAdd(&g_bar, 1);
    if (b != 0 || pass != 0) return;

    if (t == 0) {
        volatile int* vb = &g_bar;
        while (*vb < 16) { }
    }
    __syncthreads();
    __threadfence();

    // ---- fused SSIM: warp w -> image w + fixed-order mean ----
    float* sl = pool;
    if (warp < BATCH) {
        const float* cx = g_corr + (size_t)warp * 2048;
        const float* cy = cx + 1024;
        float sx = 0.0f, sy = 0.0f;
        for (int i = lane; i < 1024; i += 32) { sx += cx[i]; sy += cy[i]; }
        #pragma unroll
        for (int o = 16; o > 0; o >>= 1) {
            sx += __shfl_xor_sync(0xffffffffu, sx, o);
            sy += __shfl_xor_sync(0xffffffffu, sy, o);
        }
        const float mux = sx / 1024.0f;
        const float muy = sy / 1024.0f;
        float ax = 0.0f, ay = 0.0f, axy = 0.0f;
        for (int i = lane; i < 1024; i += 32) {
            const float dx = cx[i] - mux;
            const float dy = cy[i] - muy;
            ax += dx * dx; ay += dy * dy; axy += dx * dy;
        }
        #pragma unroll
        for (int o = 16; o > 0; o >>= 1) {
            ax  += __shfl_xor_sync(0xffffffffu, ax, o);
            ay  += __shfl_xor_sync(0xffffffffu, ay, o);
            axy += __shfl_xor_sync(0xffffffffu, axy, o);
        }
        if (lane == 0) {
            const float vx = ax / 1023.0f, vy = ay / 1023.0f, cxy = axy / 1024.0f;
            const float C1 = 1e-4f, C2 = 1e-4f;
            const float num = (2.0f * mux * muy + C1) * (2.0f * cxy + C2);
            const float den = (mux * mux + muy * muy + C1) * (vx + vy + C2);
            float ssim = num / den;
            ssim = fminf(1.0f, fmaxf(0.0f, ssim));
            sl[warp] = 1.0f - ssim;
        }
    }
    __syncthreads();
    if (t == 0) {
        float s = 0.0f;
        #pragma unroll
        for (int i = 0; i < BATCH; i++) s += sl[i];
        out[0] = s / (float)BATCH;
        g_bar = 0;
    }
}

__global__ __launch_bounds__(512) void graph_kernel(
    const float* __restrict__ HE, const float* __restrict__ HQ,
    const int* __restrict__ MASK,
    const float* __restrict__ w1, const float* __restrict__ b1,
    const float* __restrict__ w2, const float* __restrict__ b2,
    float* __restrict__ out)
{
    __shared__ __align__(16) float pool[POOLSZ];
    __shared__ int s_sel;

    const int b = blockIdx.x;
    const int pass = blockIdx.y;
    const int* mb = MASK + (size_t)b * NCELL * IMG;

    if (pass == 0) {
        graph_body<3>(HE + (size_t)b * 3 * IMG, mb, w1, b1, w2, b2, out, pool, &s_sel, b, 0);
    } else {
        graph_body<GCH>(HQ + (size_t)b * GCH * IMG, mb, w1, b1, w2, b2, out, pool, &s_sel, b, 1);
    }
}

extern "C" void kernel_launch(void* const* d_in, const int* in_sizes, int n_in,
                              void* d_out, int out_size) {
    (void)in_sizes; (void)n_in; (void)out_size;
    const float* HE   = (const float*)d_in[0];
    const float* HQ   = (const float*)d_in[1];
    const int*   MASK = (const int*)d_in[2];
    const float* w1   = (const float*)d_in[3];
    const float* b1   = (const float*)d_in[4];
    const float* w2   = (const float*)d_in[5];
    const float* b2   = (const float*)d_in[6];

    ent_kernel<<<dim3(256, BATCH), 128>>>(HE);
    graph_kernel<<<dim3(BATCH, 2), 512>>>(HE, HQ, MASK, w1, b1, w2, b2, (float*)d_out);
}

// round 6
// speedup vs baseline: 1.0985x; 1.0941x over previous
#include <cuda_runtime.h>
#include <cuda_bf16.h>
#include <math.h>

#define BATCH 8
#define HDIM  512
#define WDIM  512
#define NPATCH 1024
#define PATCH 16
#define NCELL 32
#define GCH   20
#define FEAT  64
#define IMG   (HDIM*WDIM)

// Scratch (no allocation allowed)
__device__ unsigned long long g_bmax[BATCH * 256];
__device__ float g_feat[BATCH * NCELL * 24];   // 0-2: E_HE, 3-22: E_HQ
__device__ float g_coord[BATCH * NCELL * 2];
__device__ float g_corr[BATCH * 2 * NCELL * NCELL];
__device__ int   g_bar = 0;

// ---------------------------------------------------------------------------
// Kernel 1: per-patch entropy, warp per patch. grid (256,8), block 128.
// ---------------------------------------------------------------------------
__global__ __launch_bounds__(128) void ent_kernel(const float* __restrict__ HE) {
    __shared__ int hist[4][256];
    __shared__ unsigned long long keys[4];

    const int t = threadIdx.x, warp = t >> 5, lane = t & 31;
    const int p = blockIdx.x * 4 + warp;
    const int b = blockIdx.y;
    const int y00 = (p >> 5) * PATCH;
    const int x00 = (p & 31) * PATCH;
    const float* base = HE + (size_t)b * 3 * IMG;

    const size_t off = (size_t)(y00 + (lane >> 1)) * WDIM + x00 + (lane & 1) * 8;
    const float4 r0 = *(const float4*)(base + off);
    const float4 r1 = *(const float4*)(base + off + 4);
    const float4 g0 = *(const float4*)(base + IMG + off);
    const float4 g1 = *(const float4*)(base + IMG + off + 4);
    const float4 b0 = *(const float4*)(base + 2 * IMG + off);
    const float4 b1 = *(const float4*)(base + 2 * IMG + off + 4);

    float gv[8];
    gv[0] = 0.2989f * r0.x + 0.587f * g0.x + 0.114f * b0.x;
    gv[1] = 0.2989f * r0.y + 0.587f * g0.y + 0.114f * b0.y;
    gv[2] = 0.2989f * r0.z + 0.587f * g0.z + 0.114f * b0.z;
    gv[3] = 0.2989f * r0.w + 0.587f * g0.w + 0.114f * b0.w;
    gv[4] = 0.2989f * r1.x + 0.587f * g1.x + 0.114f * b1.x;
    gv[5] = 0.2989f * r1.y + 0.587f * g1.y + 0.114f * b1.y;
    gv[6] = 0.2989f * r1.z + 0.587f * g1.z + 0.114f * b1.z;
    gv[7] = 0.2989f * r1.w + 0.587f * g1.w + 0.114f * b1.w;

    float mn = gv[0], mx = gv[0];
    #pragma unroll
    for (int j = 1; j < 8; j++) { mn = fminf(mn, gv[j]); mx = fmaxf(mx, gv[j]); }
    #pragma unroll
    for (int o = 16; o > 0; o >>= 1) {
        mn = fminf(mn, __shfl_xor_sync(0xffffffffu, mn, o));
        mx = fmaxf(mx, __shfl_xor_sync(0xffffffffu, mx, o));
    }

    ((int4*)hist[warp])[lane]      = make_int4(0, 0, 0, 0);
    ((int4*)hist[warp])[lane + 32] = make_int4(0, 0, 0, 0);
    __syncwarp();

    const float den = (mx - mn) + 1e-8f;
    const float rs = 256.0f / den;
    #pragma unroll
    for (int j = 0; j < 8; j++) {
        const float r = gv[j] - mn;
        const float q = r * rs;
        const float fq = floorf(q);
        int bin;
        const float frac = q - fq;
        if (frac < 5e-4f || frac > 1.0f - 5e-4f) {
            bin = (int)((r / den) * 256.0f);      // exact reference path
        } else {
            bin = (int)fq;
        }
        bin = min(255, max(0, bin));
        atomicAdd(&hist[warp][bin], 1);
    }
    __syncwarp();

    const int4 c0 = ((const int4*)hist[warp])[lane];
    const int4 c1 = ((const int4*)hist[warp])[lane + 32];
    float e = 0.0f;
    {
        const int cs[8] = {c0.x, c0.y, c0.z, c0.w, c1.x, c1.y, c1.z, c1.w};
        #pragma unroll
        for (int j = 0; j < 8; j++) {
            if (cs[j] > 0) {
                const float pr = (float)cs[j] * (1.0f / 256.0f);
                e += pr * log2f(pr);
            }
        }
    }
    #pragma unroll
    for (int o = 16; o > 0; o >>= 1) e += __shfl_xor_sync(0xffffffffu, e, o);

    const float ent = fmaxf(-e, 0.0f);
    const unsigned long long key =
        ((unsigned long long)__float_as_uint(ent) << 32) | (unsigned)(NPATCH - 1 - p);
    if (lane == 0) keys[warp] = key;
    __syncthreads();
    if (t == 0) {
        unsigned long long k = keys[0];
        #pragma unroll
        for (int w = 1; w < 4; w++) k = (keys[w] > k) ? keys[w] : k;
        g_bmax[b * 256 + blockIdx.x] = k;
    }
}

// ---------------------------------------------------------------------------
// Kernel 2: per-(image,cell) masked stats. grid (32 cells, 8 images), block 128.
// Each block: argmax reduce -> gather one cell's mask + 23 channels -> E, coords.
// ---------------------------------------------------------------------------
__global__ __launch_bounds__(128) void stats_kernel(
    const float* __restrict__ HE, const float* __restrict__ HQ,
    const int* __restrict__ MASK)
{
    const int cell = blockIdx.x, b = blockIdx.y;
    const int t = threadIdx.x, lane = t & 31, warp = t >> 5;

    __shared__ unsigned long long sk[4];
    __shared__ float part[4][26];
    __shared__ float tot[26];
    __shared__ int s_sel;

    // ---- argmax over 256 per-block entropy keys ----
    {
        unsigned long long k  = g_bmax[b * 256 + t];
        const unsigned long long k2 = g_bmax[b * 256 + t + 128];
        k = (k2 > k) ? k2 : k;
        #pragma unroll
        for (int o = 16; o > 0; o >>= 1) {
            const unsigned long long v = __shfl_xor_sync(0xffffffffu, k, o);
            k = (v > k) ? v : k;
        }
        if (lane == 0) sk[warp] = k;
        __syncthreads();
        if (t == 0) {
            unsigned long long m = sk[0];
            #pragma unroll
            for (int w = 1; w < 4; w++) m = (sk[w] > m) ? sk[w] : m;
            s_sel = NPATCH - 1 - (int)(unsigned)(m & 0xffffffffu);
        }
        __syncthreads();
    }
    const int sel = s_sel;
    const int y0 = (sel >> 5) * PATCH;
    const int x0 = (sel & 31) * PATCH;

    // ---- gather: thread covers pixels 2t, 2t+1 ----
    const int py  = t >> 3;           // 0..15
    const int px0 = (t & 7) * 2;      // 0,2,...,14
    const size_t poff = (size_t)(y0 + py) * WDIM + x0 + px0;

    const int2 mi = *(const int2*)&MASK[((size_t)(b * NCELL + cell) * HDIM * WDIM) + poff];
    const float m0 = (float)mi.x, m1 = (float)mi.y;

    float vals[26];
    vals[0] = m0 + m1;                                    // sm
    vals[1] = m0 * (float)px0 + m1 * (float)(px0 + 1);    // sx
    vals[2] = (m0 + m1) * (float)py;                      // sy
    #pragma unroll
    for (int c = 0; c < 3; c++) {
        const float2 v = *(const float2*)&HE[((size_t)(b * 3 + c)) * IMG + poff];
        vals[3 + c] = m0 * v.x + m1 * v.y;
    }
    #pragma unroll
    for (int c = 0; c < GCH; c++) {
        const float2 v = *(const float2*)&HQ[((size_t)(b * GCH + c)) * IMG + poff];
        vals[6 + c] = m0 * v.x + m1 * v.y;
    }

    #pragma unroll
    for (int o = 16; o > 0; o >>= 1) {
        #pragma unroll
        for (int i = 0; i < 26; i++)
            vals[i] += __shfl_down_sync(0xffffffffu, vals[i], o);
    }
    if (lane == 0) {
        #pragma unroll
        for (int i = 0; i < 26; i++) part[warp][i] = vals[i];
    }
    __syncthreads();
    if (t < 26) tot[t] = part[0][t] + part[1][t] + part[2][t] + part[3][t];
    __syncthreads();

    if (t < 23) {
        g_feat[(size_t)(b * NCELL + cell) * 24 + t] = tot[3 + t] / (tot[0] + 1e-6f);
    } else if (t == 23) {
        g_coord[(b * NCELL + cell) * 2 + 0] = tot[1] / tot[0];
        g_coord[(b * NCELL + cell) * 2 + 1] = tot[2] / tot[0];
    }
}

// ---------------------------------------------------------------------------
// Kernel 3: pure on-chip math. grid (8,2), block 256.
// ---------------------------------------------------------------------------
#define STRX 24
#define STR  68

template<int NCH>
__device__ __forceinline__ void math_body(
    const float* __restrict__ w1, const float* __restrict__ b1,
    const float* __restrict__ w2, const float* __restrict__ b2,
    float* __restrict__ out, float* pool, int b, int pass)
{
    const int t = threadIdx.x;
    const int lane = t & 31, warp = t >> 5;

    float* Xs     = pool;                  // [32][24]
    float* adjs   = pool + 768;            // [32][33] = 1056
    float* coordS = pool + 1824;           // [64]
    float* rowS   = pool + 1888;           // [32]
    float* Gs     = pool + 1920;           // [32][68] = 2176
    float* bufS   = pool + 4096;           // [32][68] = 2176
    float* ws     = pool + 6272;           // [64][68] = 4352  -> total 10624

    // ---- load feats + coords (+ w1T) ----
    for (int i = t; i < NCELL * NCH; i += 256) {
        const int cell = i / NCH, c = i - cell * NCH;
        Xs[cell * STRX + c] = g_feat[(size_t)(b * NCELL + cell) * 24 + (pass ? 3 + c : c)];
    }
    if (t >= 192 && t < 256) coordS[t - 192] = g_coord[b * NCELL * 2 + (t - 192)];
    for (int i = t; i < FEAT * FEAT; i += 256) ws[(i & 63) * STR + (i >> 6)] = w1[i];
    __syncthreads();

    // ---- adjacency ----
    for (int i = t; i < NCELL * NCELL; i += 256) {
        const int r_ = i >> 5, c_ = i & 31;
        const float dx = coordS[r_ * 2] - coordS[c_ * 2];
        const float dy = coordS[r_ * 2 + 1] - coordS[c_ * 2 + 1];
        const float dist = sqrtf(fmaxf(dx * dx + dy * dy, 0.0f));
        adjs[r_ * 33 + c_] = expf(-dist / 3.000001f);
    }
    __syncthreads();
    if (t < NCELL) {
        float s = 0.0f;
        #pragma unroll
        for (int k = 0; k < NCELL; k++) s += adjs[t * 33 + k];
        rowS[t] = s + 1e-8f;
    }
    __syncthreads();
    for (int i = t; i < NCELL * NCELL; i += 256)
        adjs[(i >> 5) * 33 + (i & 31)] /= rowS[i >> 5];
    __syncthreads();

    // m1: bufS[32][NCH] = adj @ X
    for (int o = t; o < NCELL * NCH; o += 256) {
        const int r = o / NCH, c = o - r * NCH;
        float acc = 0.0f;
        #pragma unroll
        for (int k = 0; k < NCELL; k++) acc += adjs[r * 33 + k] * Xs[k * STRX + c];
        bufS[r * STR + c] = acc;
    }
    __syncthreads();

    const int r_ = t >> 3;          // 0..31
    const int c8 = (t & 7) * 8;     // 0,8,...,56

    // m2: Gs = relu(bufS @ w1^T + b1), K = NCH
    {
        float a[8] = {0,0,0,0,0,0,0,0};
        #pragma unroll
        for (int k = 0; k < NCH; k++) {
            const float tv = bufS[r_ * STR + k];
            const float4 wA = *(const float4*)&ws[k * STR + c8];
            const float4 wB = *(const float4*)&ws[k * STR + c8 + 4];
            a[0] += tv * wA.x; a[1] += tv * wA.y; a[2] += tv * wA.z; a[3] += tv * wA.w;
            a[4] += tv * wB.x; a[5] += tv * wB.y; a[6] += tv * wB.z; a[7] += tv * wB.w;
        }
        const float4 bA = *(const float4*)&b1[c8];
        const float4 bB = *(const float4*)&b1[c8 + 4];
        *(float4*)&Gs[r_ * STR + c8] = make_float4(
            fmaxf(a[0] + bA.x, 0.0f), fmaxf(a[1] + bA.y, 0.0f),
            fmaxf(a[2] + bA.z, 0.0f), fmaxf(a[3] + bA.w, 0.0f));
        *(float4*)&Gs[r_ * STR + c8 + 4] = make_float4(
            fmaxf(a[4] + bB.x, 0.0f), fmaxf(a[5] + bB.y, 0.0f),
            fmaxf(a[6] + bB.z, 0.0f), fmaxf(a[7] + bB.w, 0.0f));
    }
    __syncthreads();

    // m3: bufS = adj @ Gs (K=32) ; then load w2T
    {
        float a[8] = {0,0,0,0,0,0,0,0};
        #pragma unroll
        for (int k = 0; k < NCELL; k++) {
            const float av = adjs[r_ * 33 + k];
            const float4 gA = *(const float4*)&Gs[k * STR + c8];
            const float4 gB = *(const float4*)&Gs[k * STR + c8 + 4];
            a[0] += av * gA.x; a[1] += av * gA.y; a[2] += av * gA.z; a[3] += av * gA.w;
            a[4] += av * gB.x; a[5] += av * gB.y; a[6] += av * gB.z; a[7] += av * gB.w;
        }
        *(float4*)&bufS[r_ * STR + c8]     = make_float4(a[0], a[1], a[2], a[3]);
        *(float4*)&bufS[r_ * STR + c8 + 4] = make_float4(a[4], a[5], a[6], a[7]);
    }
    __syncthreads();
    for (int i = t; i < FEAT * FEAT; i += 256) ws[(i & 63) * STR + (i >> 6)] = w2[i];
    __syncthreads();

    // m4: Gs = relu(bufS @ w2^T + b2), K = 64
    {
        float a[8] = {0,0,0,0,0,0,0,0};
        #pragma unroll
        for (int k = 0; k < FEAT; k++) {
            const float tv = bufS[r_ * STR + k];
            const float4 wA = *(const float4*)&ws[k * STR + c8];
            const float4 wB = *(const float4*)&ws[k * STR + c8 + 4];
            a[0] += tv * wA.x; a[1] += tv * wA.y; a[2] += tv * wA.z; a[3] += tv * wA.w;
            a[4] += tv * wB.x; a[5] += tv * wB.y; a[6] += tv * wB.z; a[7] += tv * wB.w;
        }
        const float4 bA = *(const float4*)&b2[c8];
        const float4 bB = *(const float4*)&b2[c8 + 4];
        *(float4*)&Gs[r_ * STR + c8] = make_float4(
            fmaxf(a[0] + bA.x, 0.0f), fmaxf(a[1] + bA.y, 0.0f),
            fmaxf(a[2] + bA.z, 0.0f), fmaxf(a[3] + bA.w, 0.0f));
        *(float4*)&Gs[r_ * STR + c8 + 4] = make_float4(
            fmaxf(a[4] + bB.x, 0.0f), fmaxf(a[5] + bB.y, 0.0f),
            fmaxf(a[6] + bB.z, 0.0f), fmaxf(a[7] + bB.w, 0.0f));
    }
    __syncthreads();

    // ---- standardize the NCH live X cols + 64 G cols (ddof=1) ----
    if (t < NCH + FEAT) {
        const bool isX = (t < NCH);
        float* M = isX ? (Xs + t) : (Gs + (t - NCH));
        const int str = isX ? STRX : STR;
        float mean = 0.0f;
        #pragma unroll
        for (int rr = 0; rr < NCELL; rr++) mean += M[rr * str];
        mean *= (1.0f / (float)NCELL);
        float vs = 0.0f;
        #pragma unroll
        for (int rr = 0; rr < NCELL; rr++) {
            const float d = M[rr * str] - mean;
            vs += d * d;
        }
        const float dn = sqrtf(vs / (float)(NCELL - 1)) + 1e-6f;
        #pragma unroll
        for (int rr = 0; rr < NCELL; rr++) M[rr * str] = (M[rr * str] - mean) / dn;
    }
    __syncthreads();

    // ---- corr = clip(Z Z^T / 127, -1, 1): symmetric ----
    {
        float* dst = g_corr + ((size_t)b * 2 + pass) * (NCELL * NCELL);
        for (int i = t; i < NCELL * NCELL; i += 256) {
            const int cr = i >> 5, cc = i & 31;
            if (cr > cc) continue;
            float acc = 0.0f;
            if (NCH == GCH) {
                #pragma unroll
                for (int kk = 0; kk < 5; kk++) {
                    const float4 a = *(const float4*)&Xs[cr * STRX + kk * 4];
                    const float4 v = *(const float4*)&Xs[cc * STRX + kk * 4];
                    acc += a.x * v.x; acc += a.y * v.y; acc += a.z * v.z; acc += a.w * v.w;
                }
            } else {
                #pragma unroll
                for (int kk = 0; kk < NCH; kk++) acc += Xs[cr * STRX + kk] * Xs[cc * STRX + kk];
            }
            #pragma unroll
            for (int kk = 0; kk < 16; kk++) {
                const float4 a = *(const float4*)&Gs[cr * STR + kk * 4];
                const float4 v = *(const float4*)&Gs[cc * STR + kk * 4];
                acc += a.x * v.x; acc += a.y * v.y; acc += a.z * v.z; acc += a.w * v.w;
            }
            float v = acc * (1.0f / 127.0f);
            v = fminf(1.0f, fmaxf(-1.0f, v));
            dst[cr * NCELL + cc] = v;
            dst[cc * NCELL + cr] = v;
        }
    }

    // ---- inter-block barrier (16 co-resident blocks) ----
    __threadfence();
    __syncthreads();
    if (t == 0) atomicAdd(&g_bar, 1);
    if (b != 0 || pass != 0) return;

    if (t == 0) {
        volatile int* vb = &g_bar;
        while (*vb < 16) { }
    }
    __syncthreads();
    __threadfence();

    // ---- fused SSIM: warp w -> image w (8 warps) + fixed-order mean ----
    float* sl = pool;
    {
        const float* cx = g_corr + (size_t)warp * 2048;
        const float* cy = cx + 1024;
        float sx = 0.0f, sy = 0.0f;
        for (int i = lane; i < 1024; i += 32) { sx += cx[i]; sy += cy[i]; }
        #pragma unroll
        for (int o = 16; o > 0; o >>= 1) {
            sx += __shfl_xor_sync(0xffffffffu, sx, o);
            sy += __shfl_xor_sync(0xffffffffu, sy, o);
        }
        const float mux = sx / 1024.0f;
        const float muy = sy / 1024.0f;
        float ax = 0.0f, ay = 0.0f, axy = 0.0f;
        for (int i = lane; i < 1024; i += 32) {
            const float dx = cx[i] - mux;
            const float dy = cy[i] - muy;
            ax += dx * dx; ay += dy * dy; axy += dx * dy;
        }
        #pragma unroll
        for (int o = 16; o > 0; o >>= 1) {
            ax  += __shfl_xor_sync(0xffffffffu, ax, o);
            ay  += __shfl_xor_sync(0xffffffffu, ay, o);
            axy += __shfl_xor_sync(0xffffffffu, axy, o);
        }
        if (lane == 0) {
            const float vx = ax / 1023.0f, vy = ay / 1023.0f, cxy = axy / 1024.0f;
            const float C1 = 1e-4f, C2 = 1e-4f;
            const float num = (2.0f * mux * muy + C1) * (2.0f * cxy + C2);
            const float den = (mux * mux + muy * muy + C1) * (vx + vy + C2);
            float ssim = num / den;
            ssim = fminf(1.0f, fmaxf(0.0f, ssim));
            sl[warp] = 1.0f - ssim;
        }
    }
    __syncthreads();
    if (t == 0) {
        float s = 0.0f;
        #pragma unroll
        for (int i = 0; i < BATCH; i++) s += sl[i];
        out[0] = s / (float)BATCH;
        g_bar = 0;
    }
}

__global__ __launch_bounds__(256) void math_kernel(
    const float* __restrict__ w1, const float* __restrict__ b1,
    const float* __restrict__ w2, const float* __restrict__ b2,
    float* __restrict__ out)
{
    __shared__ __align__(16) float pool[10624];
    const int b = blockIdx.x;
    const int pass = blockIdx.y;
    if (pass == 0) math_body<3>(w1, b1, w2, b2, out, pool, b, 0);
    else           math_body<GCH>(w1, b1, w2, b2, out, pool, b, 1);
}

extern "C" void kernel_launch(void* const* d_in, const int* in_sizes, int n_in,
                              void* d_out, int out_size) {
    (void)in_sizes; (void)n_in; (void)out_size;
    const float* HE   = (const float*)d_in[0];
    const float* HQ   = (const float*)d_in[1];
    const int*   MASK = (const int*)d_in[2];
    const float* w1   = (const float*)d_in[3];
    const float* b1   = (const float*)d_in[4];
    const float* w2   = (const float*)d_in[5];
    const float* b2   = (const float*)d_in[6];

    ent_kernel<<<dim3(256, BATCH), 128>>>(HE);
    stats_kernel<<<dim3(NCELL, BATCH), 128>>>(HE, HQ, MASK);
    math_kernel<<<dim3(BATCH, 2), 256>>>(w1, b1, w2, b2, (float*)d_out);
}